// round 3
// baseline (speedup 1.0000x reference)
#include <cuda_runtime.h>
#include <cstdint>
#include <math.h>

#define NPB 64000   // positions per batch (40*40*40)
#define CCH 96

// ---------------- scratch (device globals; no allocation) ----------------
__device__ __align__(128) float g_buf0[2u * 96 * 64000];
__device__ __align__(128) float g_buf1[2u * 96 * 64000];
__device__ __align__(128) float g_buf2[2u * 96 * 64000];
__device__ __align__(128) float g_qkv [2u * 288 * 64000];
__device__ __align__(128) float g_stats[2 * 96 * 2];

__device__ __forceinline__ float gelu_f(float x) {
    return 0.5f * x * (1.0f + erff(x * 0.70710678118654752f));
}

// ---------------- instance-norm stats: one block per (b,c) ----------------
__global__ void stats_kernel(const float* __restrict__ X, float* __restrict__ st) {
    int bc = blockIdx.x;   // 0..191
    const float* p = X + (size_t)bc * NPB;
    float s = 0.f, s2 = 0.f;
    for (int i = threadIdx.x; i < NPB; i += 256) {
        float v = p[i];
        s += v; s2 += v * v;
    }
    __shared__ float sh0[256], sh1[256];
    int t = threadIdx.x;
    sh0[t] = s; sh1[t] = s2;
    __syncthreads();
    for (int o = 128; o > 0; o >>= 1) {
        if (t < o) { sh0[t] += sh0[t + o]; sh1[t] += sh1[t + o]; }
        __syncthreads();
    }
    if (t == 0) {
        float mu = sh0[0] * (1.0f / NPB);
        float var = sh1[0] * (1.0f / NPB) - mu * mu;
        var = fmaxf(var, 0.f);
        st[bc * 2 + 0] = mu;
        st[bc * 2 + 1] = rsqrtf(var + 1e-5f);
    }
}

// ---------------- 1x1-conv GEMM: Y[b][m][n] = sum_k A[m][k] * T(X[b][k][n]) + bias
// NORM_IN: T(v) = gelu((v - mean[k]) * rstd[k]);  EPI==1: y = aux * sigmoid(y)
template<bool NORM_IN, int EPI>
__global__ __launch_bounds__(256)
void gemm1x1_kernel(const float* __restrict__ A, const float* __restrict__ bias,
                    const float* __restrict__ X, const float* __restrict__ st,
                    const float* __restrict__ aux, float* __restrict__ Y, int Mtot) {
    int b  = blockIdx.z;
    int n0 = blockIdx.x * 128;
    int m0 = blockIdx.y * 96;
    const float* Xb = X + (size_t)b * 96 * NPB;

    __shared__ float As[16][96];
    __shared__ float Bs[16][128];

    int tid = threadIdx.x;
    int tx = tid & 15, ty = tid >> 4;
    float acc[6][8];
#pragma unroll
    for (int i = 0; i < 6; i++)
#pragma unroll
        for (int j = 0; j < 8; j++) acc[i][j] = 0.f;

    int r  = tid >> 5;   // 0..7
    int c4 = tid & 31;   // 0..31

    for (int k0 = 0; k0 < 96; k0 += 16) {
        // A tile: 96x16, stored transposed As[k][m]
#pragma unroll
        for (int i = 0; i < 6; i++) {
            int lin = tid + i * 256;
            int m = lin % 96, k = lin / 96;
            As[k][m] = A[(size_t)(m0 + m) * 96 + k0 + k];
        }
        // B tile: 16x128, float4, coalesced
#pragma unroll
        for (int rr = 0; rr < 2; rr++) {
            int krow = r + rr * 8;
            int k = k0 + krow;
            float4 v = *(const float4*)(Xb + (size_t)k * NPB + n0 + c4 * 4);
            if (NORM_IN) {
                float mu = st[(b * 96 + k) * 2 + 0];
                float rs = st[(b * 96 + k) * 2 + 1];
                v.x = gelu_f((v.x - mu) * rs);
                v.y = gelu_f((v.y - mu) * rs);
                v.z = gelu_f((v.z - mu) * rs);
                v.w = gelu_f((v.w - mu) * rs);
            }
            *(float4*)&Bs[krow][c4 * 4] = v;
        }
        __syncthreads();
#pragma unroll
        for (int kk = 0; kk < 16; kk++) {
            float a[6], bb[8];
#pragma unroll
            for (int i = 0; i < 6; i++) a[i] = As[kk][ty * 6 + i];
#pragma unroll
            for (int j = 0; j < 8; j++) bb[j] = Bs[kk][tx * 8 + j];
#pragma unroll
            for (int i = 0; i < 6; i++)
#pragma unroll
                for (int j = 0; j < 8; j++)
                    acc[i][j] = fmaf(a[i], bb[j], acc[i][j]);
        }
        __syncthreads();
    }

#pragma unroll
    for (int i = 0; i < 6; i++) {
        int m = m0 + ty * 6 + i;
        float bv = bias[m];
        float* yr = Y + ((size_t)b * Mtot + m) * NPB + n0 + tx * 8;
        if (EPI == 0) {
            float4 o0 = make_float4(acc[i][0] + bv, acc[i][1] + bv, acc[i][2] + bv, acc[i][3] + bv);
            float4 o1 = make_float4(acc[i][4] + bv, acc[i][5] + bv, acc[i][6] + bv, acc[i][7] + bv);
            *(float4*)(yr)     = o0;
            *(float4*)(yr + 4) = o1;
        } else {
            const float* ar = aux + ((size_t)b * 96 + m) * NPB + n0 + tx * 8;
            float4 x0 = *(const float4*)(ar);
            float4 x1 = *(const float4*)(ar + 4);
            float4 o0, o1;
            o0.x = x0.x / (1.f + __expf(-(acc[i][0] + bv)));
            o0.y = x0.y / (1.f + __expf(-(acc[i][1] + bv)));
            o0.z = x0.z / (1.f + __expf(-(acc[i][2] + bv)));
            o0.w = x0.w / (1.f + __expf(-(acc[i][3] + bv)));
            o1.x = x1.x / (1.f + __expf(-(acc[i][4] + bv)));
            o1.y = x1.y / (1.f + __expf(-(acc[i][5] + bv)));
            o1.z = x1.z / (1.f + __expf(-(acc[i][6] + bv)));
            o1.w = x1.w / (1.f + __expf(-(acc[i][7] + bv)));
            *(float4*)(yr)     = o0;
            *(float4*)(yr + 4) = o1;
        }
    }
}

// ---------------- conv 3x3x3 circular as implicit GEMM, K = 96*27 = 2592 ----------------
// W row-major [96][2592] (== lp1_w layout: oc, ic, kd, kh, kw), B gathered with wrap.
__global__ __launch_bounds__(256)
void conv3_kernel(const float* __restrict__ W, const float* __restrict__ bias,
                  const float* __restrict__ X, float* __restrict__ Y) {
    int b  = blockIdx.z;
    int n0 = blockIdx.x * 128;
    const float* Xb = X + (size_t)b * 96 * NPB;
    float* Yb = Y + (size_t)b * 96 * NPB;

    __shared__ float As[16][96];
    __shared__ float Bs[16][128];

    int tid = threadIdx.x;
    int tx = tid & 15, ty = tid >> 4;
    float acc[6][8];
#pragma unroll
    for (int i = 0; i < 6; i++)
#pragma unroll
        for (int j = 0; j < 8; j++) acc[i][j] = 0.f;

    // decode the 8 spatial columns this thread gathers (row = ty, cols = tx + j*16)
    int dcol[8], hcol[8], wcol[8];
#pragma unroll
    for (int j = 0; j < 8; j++) {
        int p = n0 + tx + j * 16;
        dcol[j] = p / 1600;
        hcol[j] = (p / 40) % 40;
        wcol[j] = p % 40;
    }

    for (int k0 = 0; k0 < 2592; k0 += 16) {
        // A tile
#pragma unroll
        for (int i = 0; i < 6; i++) {
            int lin = tid + i * 256;
            int m = lin % 96, k = lin / 96;
            As[k][m] = W[(size_t)m * 2592 + k0 + k];
        }
        // B tile: gathered with circular wrap
        {
            int k = k0 + ty;
            int ic = k / 27, t = k % 27;
            int dd = t / 9 - 1, hh = (t / 3) % 3 - 1, ww = t % 3 - 1;
            const float* Xc = Xb + (size_t)ic * NPB;
#pragma unroll
            for (int j = 0; j < 8; j++) {
                int d2 = dcol[j] + dd; if (d2 < 0) d2 += 40; else if (d2 >= 40) d2 -= 40;
                int h2 = hcol[j] + hh; if (h2 < 0) h2 += 40; else if (h2 >= 40) h2 -= 40;
                int w2 = wcol[j] + ww; if (w2 < 0) w2 += 40; else if (w2 >= 40) w2 -= 40;
                Bs[ty][tx + j * 16] = Xc[d2 * 1600 + h2 * 40 + w2];
            }
        }
        __syncthreads();
#pragma unroll
        for (int kk = 0; kk < 16; kk++) {
            float a[6], bb[8];
#pragma unroll
            for (int i = 0; i < 6; i++) a[i] = As[kk][ty * 6 + i];
#pragma unroll
            for (int j = 0; j < 8; j++) bb[j] = Bs[kk][tx * 8 + j];
#pragma unroll
            for (int i = 0; i < 6; i++)
#pragma unroll
                for (int j = 0; j < 8; j++)
                    acc[i][j] = fmaf(a[i], bb[j], acc[i][j]);
        }
        __syncthreads();
    }

#pragma unroll
    for (int i = 0; i < 6; i++) {
        int m = ty * 6 + i;
        float bv = bias[m];
        float* yr = Yb + (size_t)m * NPB + n0 + tx * 8;
        float4 o0 = make_float4(acc[i][0] + bv, acc[i][1] + bv, acc[i][2] + bv, acc[i][3] + bv);
        float4 o1 = make_float4(acc[i][4] + bv, acc[i][5] + bv, acc[i][6] + bv, acc[i][7] + bv);
        *(float4*)(yr)     = o0;
        *(float4*)(yr + 4) = o1;
    }
}

// ---------------- axial attention: one block per (b, head, line) ----------------
// Rotation is an exact no-op (orthogonal R), pos_attn is an exact softmax no-op.
__global__ __launch_bounds__(128)
void attn_kernel(const float* __restrict__ QKV, float* __restrict__ OS,
                 int axis, int accum) {
    __shared__ float sq[40][25], sk[40][25], sv[40][25];
    __shared__ float S[40][41];

    int b = blockIdx.z, head = blockIdx.y, idx = blockIdx.x;
    int base, stride;
    if (axis == 0)      { int h = idx / 40, w = idx % 40; base = h * 40 + w;       stride = 1600; }
    else if (axis == 1) { int d = idx / 40, w = idx % 40; base = d * 1600 + w;     stride = 40;   }
    else                { int d = idx / 40, h = idx % 40; base = d * 1600 + h * 40; stride = 1;   }

    const float* Qb = QKV + ((size_t)b * 288 + head * 24) * NPB + base;
    int tid = threadIdx.x;

    for (int i = tid; i < 960; i += 128) {
        int l = i % 40;
        int e = i / 40;            // 0..23
        size_t off = (size_t)e * NPB + (size_t)l * stride;
        sq[l][e] = Qb[off];
        sk[l][e] = Qb[(size_t)96 * NPB + off];
        sv[l][e] = Qb[(size_t)192 * NPB + off];
    }
    __syncthreads();

    const float scale = 0.2041241452319315f;  // 24^-0.5
    for (int p = tid; p < 1600; p += 128) {
        int i = p / 40, j = p % 40;
        float a = 0.f;
#pragma unroll
        for (int e = 0; e < 24; e++) a += sq[i][e] * sk[j][e];
        S[i][j] = a * scale;
    }
    __syncthreads();

    if (tid < 40) {
        float m = -1e30f;
#pragma unroll
        for (int j = 0; j < 40; j++) m = fmaxf(m, S[tid][j]);
        float s = 0.f;
#pragma unroll
        for (int j = 0; j < 40; j++) { float e = __expf(S[tid][j] - m); S[tid][j] = e; s += e; }
        float inv = 1.f / s;
#pragma unroll
        for (int j = 0; j < 40; j++) S[tid][j] *= inv;
    }
    __syncthreads();

    for (int p = tid; p < 960; p += 128) {
        int i = p % 40;
        int e = p / 40;           // 0..23
        float a = 0.f;
#pragma unroll
        for (int j = 0; j < 40; j++) a += S[i][j] * sv[j][e];
        float* op = OS + ((size_t)b * 96 + head * 24 + e) * NPB + base + (size_t)i * stride;
        if (accum) *op += a; else *op = a;
    }
}

// ---------------- orchestration ----------------
extern "C" void kernel_launch(void* const* d_in, const int* in_sizes, int n_in,
                              void* d_out, int out_size) {
    const float* x      = (const float*)d_in[0];
    const float* pos    = (const float*)d_in[1];
    const float* qkv_w  = (const float*)d_in[2];
    const float* qkv_b  = (const float*)d_in[3];
    const float* lp1_w  = (const float*)d_in[4];
    const float* lp1_b  = (const float*)d_in[5];
    const float* lp2_w  = (const float*)d_in[6];
    const float* lp2_b  = (const float*)d_in[7];
    const float* mod1_w = (const float*)d_in[8];
    const float* mod1_b = (const float*)d_in[9];
    const float* mod2_w = (const float*)d_in[10];
    const float* mod2_b = (const float*)d_in[11];
    // d_in[12..16]: pa_w, pa_b, R6_d, R6_h, R6_w — provably no-ops (see analysis)
    const float* proj_w = (const float*)d_in[17];
    const float* proj_b = (const float*)d_in[18];

    float *buf0, *buf1, *buf2, *qkv, *stats;
    cudaGetSymbolAddress((void**)&buf0,  g_buf0);
    cudaGetSymbolAddress((void**)&buf1,  g_buf1);
    cudaGetSymbolAddress((void**)&buf2,  g_buf2);
    cudaGetSymbolAddress((void**)&qkv,   g_qkv);
    cudaGetSymbolAddress((void**)&stats, g_stats);

    dim3 blk(256);
    dim3 g500(500, 1, 2);

    // t1 = conv3_circ(pos_emb) + lp1_b
    conv3_kernel<<<g500, blk>>>(lp1_w, lp1_b, pos, buf0);
    // instnorm stats of t1
    stats_kernel<<<192, 256>>>(buf0, stats);
    // local = gelu(norm(t1)) @ lp2
    gemm1x1_kernel<true, 0><<<g500, blk>>>(lp2_w, lp2_b, buf0, stats, nullptr, buf1, 96);
    // t2 = local @ mod1
    gemm1x1_kernel<false, 0><<<g500, blk>>>(mod1_w, mod1_b, buf1, nullptr, nullptr, buf0, 96);
    // instnorm stats of t2
    stats_kernel<<<192, 256>>>(buf0, stats);
    // x_mod = x * sigmoid(gelu(norm(t2)) @ mod2)
    gemm1x1_kernel<true, 1><<<g500, blk>>>(mod2_w, mod2_b, buf0, stats, x, buf2, 96);
    // qkv = x_mod @ qkv_w.T + qkv_b   (shared across all three axes)
    gemm1x1_kernel<false, 0><<<dim3(500, 3, 2), blk>>>(qkv_w, qkv_b, buf2, nullptr, nullptr, qkv, 288);
    // axial attention: d, h, w (accumulate into buf1)
    dim3 ga(1600, 4, 2);
    attn_kernel<<<ga, 128>>>(qkv, buf1, 0, 0);
    attn_kernel<<<ga, 128>>>(qkv, buf1, 1, 1);
    attn_kernel<<<ga, 128>>>(qkv, buf1, 2, 1);
    // out = out_sum @ proj + proj_b
    gemm1x1_kernel<false, 0><<<g500, blk>>>(proj_w, proj_b, buf1, nullptr, nullptr, (float*)d_out, 96);
}

// round 6
// speedup vs baseline: 1.0877x; 1.0877x over previous
#include <cuda_runtime.h>
#include <cstdint>
#include <math.h>

#define NPB 64000   // positions per batch (40*40*40)

// ---------------- scratch (device globals; no allocation) ----------------
__device__ __align__(128) float g_buf0[2u * 96 * 64000];
__device__ __align__(128) float g_buf1[2u * 96 * 64000];
__device__ __align__(128) float g_buf2[2u * 96 * 64000];
__device__ __align__(128) float g_qkv [2u * 288 * 64000];
__device__ __align__(128) float g_stats[2 * 96 * 2];

__device__ __forceinline__ float gelu_f(float x) {
    return 0.5f * x * (1.0f + erff(x * 0.70710678118654752f));
}

// ---------------- instance-norm stats: one block per (b,c) ----------------
__global__ void stats_kernel(const float* __restrict__ X, float* __restrict__ st) {
    int bc = blockIdx.x;   // 0..191
    const float* p = X + (size_t)bc * NPB;
    float s = 0.f, s2 = 0.f;
    for (int i = threadIdx.x; i < NPB; i += 256) {
        float v = p[i];
        s += v; s2 += v * v;
    }
    __shared__ float sh0[256], sh1[256];
    int t = threadIdx.x;
    sh0[t] = s; sh1[t] = s2;
    __syncthreads();
    for (int o = 128; o > 0; o >>= 1) {
        if (t < o) { sh0[t] += sh0[t + o]; sh1[t] += sh1[t + o]; }
        __syncthreads();
    }
    if (t == 0) {
        float mu = sh0[0] * (1.0f / NPB);
        float var = sh1[0] * (1.0f / NPB) - mu * mu;
        var = fmaxf(var, 0.f);
        st[bc * 2 + 0] = mu;
        st[bc * 2 + 1] = rsqrtf(var + 1e-5f);
    }
}

// ---------------- shared compute core: 96x128 tile, 6x8 thread tile ----------------
__device__ __forceinline__ void tile_compute(const float* __restrict__ As,   // [16][96]
                                             const float* __restrict__ Bs,   // [16][128]
                                             int tx, int ty, float acc[6][8]) {
    const float* ap = As + ty * 6;
    const float* bp = Bs + tx * 8;
#pragma unroll
    for (int kk = 0; kk < 16; kk++) {
        float2 a0 = *(const float2*)(ap + kk * 96);
        float2 a1 = *(const float2*)(ap + kk * 96 + 2);
        float2 a2 = *(const float2*)(ap + kk * 96 + 4);
        float4 b0 = *(const float4*)(bp + kk * 128);
        float4 b1 = *(const float4*)(bp + kk * 128 + 4);
        float av[6] = {a0.x, a0.y, a1.x, a1.y, a2.x, a2.y};
        float bv[8] = {b0.x, b0.y, b0.z, b0.w, b1.x, b1.y, b1.z, b1.w};
#pragma unroll
        for (int i = 0; i < 6; i++)
#pragma unroll
            for (int j = 0; j < 8; j++)
                acc[i][j] = fmaf(av[i], bv[j], acc[i][j]);
    }
}

// ---------------- 1x1-conv GEMM (double buffered) ----------------
// Y[b][m][n] = sum_k A[m][k] * T(X[b][k][n]) + bias
// NORM_IN: T(v) = gelu((v - mean[k]) * rstd[k]);  EPI==1: y = aux * sigmoid(y)
template<bool NORM_IN, int EPI>
__global__ __launch_bounds__(256, 2)
void gemm1x1_kernel(const float* __restrict__ A, const float* __restrict__ bias,
                    const float* __restrict__ X, const float* __restrict__ st,
                    const float* __restrict__ aux, float* __restrict__ Y, int Mtot) {
    int b  = blockIdx.z;
    int n0 = blockIdx.x * 128;
    int m0 = blockIdx.y * 96;
    const float* Xb = X + (size_t)b * 96 * NPB;

    __shared__ __align__(16) float As[2][16][96];
    __shared__ __align__(16) float Bs[2][16][128];

    int tid = threadIdx.x;
    int tx = tid & 15, ty = tid >> 4;
    int r  = tid >> 5;   // 0..7
    int c4 = tid & 31;   // 0..31

    float acc[6][8];
#pragma unroll
    for (int i = 0; i < 6; i++)
#pragma unroll
        for (int j = 0; j < 8; j++) acc[i][j] = 0.f;

    // prologue: tile 0 -> smem buffer 0
    {
#pragma unroll
        for (int i = 0; i < 6; i++) {
            int lin = tid + i * 256;
            int m = lin % 96, k = lin / 96;
            As[0][k][m] = A[(size_t)(m0 + m) * 96 + k];
        }
#pragma unroll
        for (int rr = 0; rr < 2; rr++) {
            int krow = r + rr * 8;
            float4 v = *(const float4*)(Xb + (size_t)krow * NPB + n0 + c4 * 4);
            if (NORM_IN) {
                float mu = st[(b * 96 + krow) * 2 + 0];
                float rs = st[(b * 96 + krow) * 2 + 1];
                v.x = gelu_f((v.x - mu) * rs);
                v.y = gelu_f((v.y - mu) * rs);
                v.z = gelu_f((v.z - mu) * rs);
                v.w = gelu_f((v.w - mu) * rs);
            }
            *(float4*)&Bs[0][krow][c4 * 4] = v;
        }
    }
    __syncthreads();

    for (int kt = 0; kt < 6; kt++) {
        int cur = kt & 1;
        float ra[6];
        float4 rb[2];
        bool more = (kt + 1 < 6);
        if (more) {
            int k0 = (kt + 1) * 16;
#pragma unroll
            for (int i = 0; i < 6; i++) {
                int lin = tid + i * 256;
                int m = lin % 96, k = lin / 96;
                ra[i] = A[(size_t)(m0 + m) * 96 + k0 + k];
            }
#pragma unroll
            for (int rr = 0; rr < 2; rr++) {
                int k = k0 + r + rr * 8;
                float4 v = *(const float4*)(Xb + (size_t)k * NPB + n0 + c4 * 4);
                if (NORM_IN) {
                    float mu = st[(b * 96 + k) * 2 + 0];
                    float rs = st[(b * 96 + k) * 2 + 1];
                    v.x = gelu_f((v.x - mu) * rs);
                    v.y = gelu_f((v.y - mu) * rs);
                    v.z = gelu_f((v.z - mu) * rs);
                    v.w = gelu_f((v.w - mu) * rs);
                }
                rb[rr] = v;
            }
        }

        tile_compute(&As[cur][0][0], &Bs[cur][0][0], tx, ty, acc);

        if (more) {
            int nxt = cur ^ 1;
#pragma unroll
            for (int i = 0; i < 6; i++) {
                int lin = tid + i * 256;
                int m = lin % 96, k = lin / 96;
                As[nxt][k][m] = ra[i];
            }
#pragma unroll
            for (int rr = 0; rr < 2; rr++)
                *(float4*)&Bs[nxt][r + rr * 8][c4 * 4] = rb[rr];
            __syncthreads();
        }
    }

#pragma unroll
    for (int i = 0; i < 6; i++) {
        int m = m0 + ty * 6 + i;
        float bv = bias[m];
        float* yr = Y + ((size_t)b * Mtot + m) * NPB + n0 + tx * 8;
        if (EPI == 0) {
            float4 o0 = make_float4(acc[i][0] + bv, acc[i][1] + bv, acc[i][2] + bv, acc[i][3] + bv);
            float4 o1 = make_float4(acc[i][4] + bv, acc[i][5] + bv, acc[i][6] + bv, acc[i][7] + bv);
            *(float4*)(yr)     = o0;
            *(float4*)(yr + 4) = o1;
        } else {
            const float* ar = aux + ((size_t)b * 96 + m) * NPB + n0 + tx * 8;
            float4 x0 = *(const float4*)(ar);
            float4 x1 = *(const float4*)(ar + 4);
            float4 o0, o1;
            o0.x = x0.x / (1.f + __expf(-(acc[i][0] + bv)));
            o0.y = x0.y / (1.f + __expf(-(acc[i][1] + bv)));
            o0.z = x0.z / (1.f + __expf(-(acc[i][2] + bv)));
            o0.w = x0.w / (1.f + __expf(-(acc[i][3] + bv)));
            o1.x = x1.x / (1.f + __expf(-(acc[i][4] + bv)));
            o1.y = x1.y / (1.f + __expf(-(acc[i][5] + bv)));
            o1.z = x1.z / (1.f + __expf(-(acc[i][6] + bv)));
            o1.w = x1.w / (1.f + __expf(-(acc[i][7] + bv)));
            *(float4*)(yr)     = o0;
            *(float4*)(yr + 4) = o1;
        }
    }
}

// ---------------- conv 3x3x3 circular as implicit GEMM, K = 2592 (double buffered) ----------------
__global__ __launch_bounds__(256, 2)
void conv3_kernel(const float* __restrict__ W, const float* __restrict__ bias,
                  const float* __restrict__ X, float* __restrict__ Y) {
    int b  = blockIdx.z;
    int n0 = blockIdx.x * 128;
    const float* Xb = X + (size_t)b * 96 * NPB;
    float* Yb = Y + (size_t)b * 96 * NPB;

    __shared__ __align__(16) float As[2][16][96];
    __shared__ __align__(16) float Bs[2][16][128];

    int tid = threadIdx.x;
    int tx = tid & 15, ty = tid >> 4;

    float acc[6][8];
#pragma unroll
    for (int i = 0; i < 6; i++)
#pragma unroll
        for (int j = 0; j < 8; j++) acc[i][j] = 0.f;

    // spatial coords of the 8 columns this thread gathers (row = ty, cols = tx + j*16)
    int dcol[8], hcol[8], wcol[8];
#pragma unroll
    for (int j = 0; j < 8; j++) {
        int p = n0 + tx + j * 16;
        dcol[j] = p / 1600;
        hcol[j] = (p / 40) % 40;
        wcol[j] = p % 40;
    }

    // prologue: tile 0
    {
#pragma unroll
        for (int i = 0; i < 6; i++) {
            int lin = tid + i * 256;
            int m = lin % 96, k = lin / 96;
            As[0][k][m] = W[(size_t)m * 2592 + k];
        }
        int k = ty;
        int ic = k / 27, t = k % 27;
        int dd = t / 9 - 1, hh = (t / 3) % 3 - 1, ww = t % 3 - 1;
        const float* Xc = Xb + (size_t)ic * NPB;
#pragma unroll
        for (int j = 0; j < 8; j++) {
            int d2 = dcol[j] + dd; if (d2 < 0) d2 += 40; else if (d2 >= 40) d2 -= 40;
            int h2 = hcol[j] + hh; if (h2 < 0) h2 += 40; else if (h2 >= 40) h2 -= 40;
            int w2 = wcol[j] + ww; if (w2 < 0) w2 += 40; else if (w2 >= 40) w2 -= 40;
            Bs[0][ty][tx + j * 16] = Xc[d2 * 1600 + h2 * 40 + w2];
        }
    }
    __syncthreads();

    for (int kt = 0; kt < 162; kt++) {
        int cur = kt & 1;
        float ra[6], rbv[8];
        bool more = (kt + 1 < 162);
        if (more) {
            int k0 = (kt + 1) * 16;
#pragma unroll
            for (int i = 0; i < 6; i++) {
                int lin = tid + i * 256;
                int m = lin % 96, k = lin / 96;
                ra[i] = W[(size_t)m * 2592 + k0 + k];
            }
            int k = k0 + ty;
            int ic = k / 27, t = k % 27;
            int dd = t / 9 - 1, hh = (t / 3) % 3 - 1, ww = t % 3 - 1;
            const float* Xc = Xb + (size_t)ic * NPB;
#pragma unroll
            for (int j = 0; j < 8; j++) {
                int d2 = dcol[j] + dd; if (d2 < 0) d2 += 40; else if (d2 >= 40) d2 -= 40;
                int h2 = hcol[j] + hh; if (h2 < 0) h2 += 40; else if (h2 >= 40) h2 -= 40;
                int w2 = wcol[j] + ww; if (w2 < 0) w2 += 40; else if (w2 >= 40) w2 -= 40;
                rbv[j] = Xc[d2 * 1600 + h2 * 40 + w2];
            }
        }

        tile_compute(&As[cur][0][0], &Bs[cur][0][0], tx, ty, acc);

        if (more) {
            int nxt = cur ^ 1;
#pragma unroll
            for (int i = 0; i < 6; i++) {
                int lin = tid + i * 256;
                int m = lin % 96, k = lin / 96;
                As[nxt][k][m] = ra[i];
            }
#pragma unroll
            for (int j = 0; j < 8; j++)
                Bs[nxt][ty][tx + j * 16] = rbv[j];
            __syncthreads();
        }
    }

#pragma unroll
    for (int i = 0; i < 6; i++) {
        int m = ty * 6 + i;
        float bv = bias[m];
        float* yr = Yb + (size_t)m * NPB + n0 + tx * 8;
        float4 o0 = make_float4(acc[i][0] + bv, acc[i][1] + bv, acc[i][2] + bv, acc[i][3] + bv);
        float4 o1 = make_float4(acc[i][4] + bv, acc[i][5] + bv, acc[i][6] + bv, acc[i][7] + bv);
        *(float4*)(yr)     = o0;
        *(float4*)(yr + 4) = o1;
    }
}

// ---------------- coalesced axial attention for axes d/h: 8 w-problems per block ----------------
// Warp p owns problem p (w = w8*8 + p). All gmem traffic is aligned float4 over 8
// consecutive w -> full 32B sectors. Rotation / pos_attn are exact no-ops (see R0 analysis).
// dyn smem: q[8][40][25] k[8][40][25] v[8][40][25] S[8][40][41]  = 148480 B
#define ATTN8_SMEM 148480
template<int ACCUM>
__global__ __launch_bounds__(256)
void attn8_kernel(const float* __restrict__ QKV, float* __restrict__ OS,
                  int stride_l, int line_mult) {
    extern __shared__ float sm[];
    float* sq = sm;            // p*1000 + l*25 + e
    float* sk = sm + 8000;
    float* sv = sm + 16000;
    float* sS = sm + 24000;    // p*1640 + i*41 + j

    int b = blockIdx.z, head = blockIdx.y, idx = blockIdx.x;
    int line = idx / 5, w8 = idx % 5;
    int base0 = line * line_mult + w8 * 8;

    const float* gq = QKV + ((size_t)b * 288 + head * 24) * NPB + base0;
    int tid = threadIdx.x;

    // cooperative coalesced load: 40l x 24e x 8w per tensor
    for (int t = tid; t < 1920; t += 256) {
        int l = t / 48;
        int rr = t % 48;
        int e = rr >> 1;
        int half = rr & 1;
        size_t g = (size_t)e * NPB + (size_t)l * stride_l + half * 4;
        float4 aq = *(const float4*)(gq + g);
        float4 ak = *(const float4*)(gq + (size_t)96 * NPB + g);
        float4 av = *(const float4*)(gq + (size_t)192 * NPB + g);
        int s = l * 25 + e;
        int pb = half * 4;
        sq[(pb + 0) * 1000 + s] = aq.x; sq[(pb + 1) * 1000 + s] = aq.y;
        sq[(pb + 2) * 1000 + s] = aq.z; sq[(pb + 3) * 1000 + s] = aq.w;
        sk[(pb + 0) * 1000 + s] = ak.x; sk[(pb + 1) * 1000 + s] = ak.y;
        sk[(pb + 2) * 1000 + s] = ak.z; sk[(pb + 3) * 1000 + s] = ak.w;
        sv[(pb + 0) * 1000 + s] = av.x; sv[(pb + 1) * 1000 + s] = av.y;
        sv[(pb + 2) * 1000 + s] = av.z; sv[(pb + 3) * 1000 + s] = av.w;
    }
    __syncthreads();

    int p = tid >> 5, lane = tid & 31;
    const float* qp = sq + p * 1000;
    const float* kp = sk + p * 1000;
    const float* vp = sv + p * 1000;
    float* Sp = sS + p * 1640;
    const float scale = 0.2041241452319315f;  // 24^-0.5

    // scores: 2x2 register tile per lane
    for (int t = lane; t < 400; t += 32) {
        int i2 = (t / 20) * 2;
        int j2 = (t % 20) * 2;
        float a00 = 0.f, a01 = 0.f, a10 = 0.f, a11 = 0.f;
#pragma unroll
        for (int e = 0; e < 24; e++) {
            float q0 = qp[i2 * 25 + e],       q1 = qp[(i2 + 1) * 25 + e];
            float k0 = kp[j2 * 25 + e],       k1 = kp[(j2 + 1) * 25 + e];
            a00 = fmaf(q0, k0, a00); a01 = fmaf(q0, k1, a01);
            a10 = fmaf(q1, k0, a10); a11 = fmaf(q1, k1, a11);
        }
        Sp[i2 * 41 + j2]           = a00 * scale;
        Sp[i2 * 41 + j2 + 1]       = a01 * scale;
        Sp[(i2 + 1) * 41 + j2]     = a10 * scale;
        Sp[(i2 + 1) * 41 + j2 + 1] = a11 * scale;
    }
    __syncwarp();

    // softmax per row (warp-private)
    for (int rr = lane; rr < 40; rr += 32) {
        float* row = Sp + rr * 41;
        float m = -1e30f;
#pragma unroll
        for (int j = 0; j < 40; j++) m = fmaxf(m, row[j]);
        float s = 0.f;
#pragma unroll
        for (int j = 0; j < 40; j++) { float e = __expf(row[j] - m); row[j] = e; s += e; }
        float inv = 1.f / s;
#pragma unroll
        for (int j = 0; j < 40; j++) row[j] *= inv;
    }
    __syncwarp();

    // AV -> overwrite q region with output (warp-private)
    float* op = sq + p * 1000;
    for (int t = lane; t < 960; t += 32) {
        int i = t / 24, e = t % 24;
        float a = 0.f;
#pragma unroll
        for (int j = 0; j < 40; j++) a = fmaf(Sp[i * 41 + j], vp[j * 25 + e], a);
        op[i * 25 + e] = a;
    }
    __syncthreads();

    // cooperative coalesced write-out
    float* go = OS + ((size_t)b * 96 + head * 24) * NPB + base0;
    for (int t = tid; t < 1920; t += 256) {
        int l = t / 48;
        int rr = t % 48;
        int e = rr >> 1;
        int half = rr & 1;
        int s = l * 25 + e;
        int pb = half * 4;
        float4 o;
        o.x = sq[(pb + 0) * 1000 + s];
        o.y = sq[(pb + 1) * 1000 + s];
        o.z = sq[(pb + 2) * 1000 + s];
        o.w = sq[(pb + 3) * 1000 + s];
        float* gp = go + (size_t)e * NPB + (size_t)l * stride_l + half * 4;
        if (ACCUM) {
            float4 old = *(const float4*)gp;
            o.x += old.x; o.y += old.y; o.z += old.z; o.w += old.w;
        }
        *(float4*)gp = o;
    }
}

// ---------------- axis-2 (w) attention: lines already contiguous ----------------
__global__ __launch_bounds__(128)
void attn_kernel(const float* __restrict__ QKV, float* __restrict__ OS) {
    __shared__ float sq[40][25], sk[40][25], sv[40][25];
    __shared__ float S[40][41];

    int b = blockIdx.z, head = blockIdx.y, idx = blockIdx.x;
    int d = idx / 40, h = idx % 40;
    int base = d * 1600 + h * 40;

    const float* Qb = QKV + ((size_t)b * 288 + head * 24) * NPB + base;
    int tid = threadIdx.x;

    for (int i = tid; i < 960; i += 128) {
        int l = i % 40;
        int e = i / 40;
        size_t off = (size_t)e * NPB + l;
        sq[l][e] = Qb[off];
        sk[l][e] = Qb[(size_t)96 * NPB + off];
        sv[l][e] = Qb[(size_t)192 * NPB + off];
    }
    __syncthreads();

    const float scale = 0.2041241452319315f;
    for (int p = tid; p < 1600; p += 128) {
        int i = p / 40, j = p % 40;
        float a = 0.f;
#pragma unroll
        for (int e = 0; e < 24; e++) a = fmaf(sq[i][e], sk[j][e], a);
        S[i][j] = a * scale;
    }
    __syncthreads();

    if (tid < 40) {
        float m = -1e30f;
#pragma unroll
        for (int j = 0; j < 40; j++) m = fmaxf(m, S[tid][j]);
        float s = 0.f;
#pragma unroll
        for (int j = 0; j < 40; j++) { float e = __expf(S[tid][j] - m); S[tid][j] = e; s += e; }
        float inv = 1.f / s;
#pragma unroll
        for (int j = 0; j < 40; j++) S[tid][j] *= inv;
    }
    __syncthreads();

    for (int p = tid; p < 960; p += 128) {
        int i = p % 40;
        int e = p / 40;
        float a = 0.f;
#pragma unroll
        for (int j = 0; j < 40; j++) a = fmaf(S[i][j], sv[j][e], a);
        float* op = OS + ((size_t)b * 96 + head * 24 + e) * NPB + base + i;
        *op += a;
    }
}

// ---------------- orchestration ----------------
extern "C" void kernel_launch(void* const* d_in, const int* in_sizes, int n_in,
                              void* d_out, int out_size) {
    const float* x      = (const float*)d_in[0];
    const float* pos    = (const float*)d_in[1];
    const float* qkv_w  = (const float*)d_in[2];
    const float* qkv_b  = (const float*)d_in[3];
    const float* lp1_w  = (const float*)d_in[4];
    const float* lp1_b  = (const float*)d_in[5];
    const float* lp2_w  = (const float*)d_in[6];
    const float* lp2_b  = (const float*)d_in[7];
    const float* mod1_w = (const float*)d_in[8];
    const float* mod1_b = (const float*)d_in[9];
    const float* mod2_w = (const float*)d_in[10];
    const float* mod2_b = (const float*)d_in[11];
    // d_in[12..16]: pa_w, pa_b, R6_d, R6_h, R6_w — provably no-ops
    const float* proj_w = (const float*)d_in[17];
    const float* proj_b = (const float*)d_in[18];

    float *buf0, *buf1, *buf2, *qkv, *stats;
    cudaGetSymbolAddress((void**)&buf0,  g_buf0);
    cudaGetSymbolAddress((void**)&buf1,  g_buf1);
    cudaGetSymbolAddress((void**)&buf2,  g_buf2);
    cudaGetSymbolAddress((void**)&qkv,   g_qkv);
    cudaGetSymbolAddress((void**)&stats, g_stats);

    cudaFuncSetAttribute(attn8_kernel<0>, cudaFuncAttributeMaxDynamicSharedMemorySize, ATTN8_SMEM);
    cudaFuncSetAttribute(attn8_kernel<1>, cudaFuncAttributeMaxDynamicSharedMemorySize, ATTN8_SMEM);

    dim3 blk(256);
    dim3 g500(500, 1, 2);

    // t1 = conv3_circ(pos_emb) + lp1_b
    conv3_kernel<<<g500, blk>>>(lp1_w, lp1_b, pos, buf0);
    // instnorm stats of t1
    stats_kernel<<<192, 256>>>(buf0, stats);
    // local = gelu(norm(t1)) @ lp2
    gemm1x1_kernel<true, 0><<<g500, blk>>>(lp2_w, lp2_b, buf0, stats, nullptr, buf1, 96);
    // t2 = local @ mod1
    gemm1x1_kernel<false, 0><<<g500, blk>>>(mod1_w, mod1_b, buf1, nullptr, nullptr, buf0, 96);
    // instnorm stats of t2
    stats_kernel<<<192, 256>>>(buf0, stats);
    // x_mod = x * sigmoid(gelu(norm(t2)) @ mod2)
    gemm1x1_kernel<true, 1><<<g500, blk>>>(mod2_w, mod2_b, buf0, stats, x, buf2, 96);
    // qkv = x_mod @ qkv_w.T + qkv_b   (shared across all three axes)
    gemm1x1_kernel<false, 0><<<dim3(500, 3, 2), blk>>>(qkv_w, qkv_b, buf2, nullptr, nullptr, qkv, 288);

    // axial attention
    dim3 ga8(200, 4, 2);
    // axis d: lines over d (stride 1600), problems = 8 consecutive w, block idx over (h, w8)
    attn8_kernel<0><<<ga8, 256, ATTN8_SMEM>>>(qkv, buf1, 1600, 40);
    // axis h: lines over h (stride 40), block idx over (d, w8)
    attn8_kernel<1><<<ga8, 256, ATTN8_SMEM>>>(qkv, buf1, 40, 1600);
    // axis w: contiguous lines
    attn_kernel<<<dim3(1600, 4, 2), 128>>>(qkv, buf1);

    // out = out_sum @ proj + proj_b
    gemm1x1_kernel<false, 0><<<g500, blk>>>(proj_w, proj_b, buf1, nullptr, nullptr, (float*)d_out, 96);
}